// round 13
// baseline (speedup 1.0000x reference)
#include <cuda_runtime.h>
#include <cuda_bf16.h>
#include <cuda_fp16.h>
#include <math.h>
#include <stdint.h>

#define D_MODEL 1024
#define N_HEADS 16
#define HD 64
#define BATCH 2
#define SEQ 2048
#define M_TOTAL (BATCH * SEQ)   // 4096
#define QKV_N (3 * D_MODEL)     // 3072
#define KDIM 1024

// ---------------- scratch (device globals; allocation-free) ----------------
__device__ __align__(256) __half g_x_hi[(size_t)M_TOTAL * KDIM];
__device__ __align__(256) __half g_x_lo[(size_t)M_TOTAL * KDIM];
__device__ __align__(256) __half g_y_hi[(size_t)M_TOTAL * KDIM];
__device__ __align__(256) __half g_y_lo[(size_t)M_TOTAL * KDIM];
__device__ __align__(256) __half g_qkv_hi[(size_t)M_TOTAL * QKV_N];
__device__ __align__(256) __half g_qkv_lo[(size_t)M_TOTAL * QKV_N];
__device__ __align__(256) __half g_wat[(size_t)QKV_N * KDIM];   // W_attn^T fp16
__device__ __align__(256) __half g_wpt[(size_t)D_MODEL * KDIM]; // W_proj^T fp16

// ---------------- helpers ----------------
__device__ __forceinline__ uint32_t smem_u32(const void* p) {
    uint32_t a;
    asm("{ .reg .u64 t; cvta.to.shared.u64 t, %1; cvt.u32.u64 %0, t; }"
        : "=r"(a) : "l"(p));
    return a;
}

__device__ __forceinline__ void cp16(uint32_t dst, const void* src) {
    asm volatile("cp.async.cg.shared.global [%0], [%1], 16;" :: "r"(dst), "l"(src));
}
#define CP_COMMIT() asm volatile("cp.async.commit_group;" ::: "memory")
#define CP_WAIT0()  asm volatile("cp.async.wait_group 0;" ::: "memory")
#define CP_WAIT1()  asm volatile("cp.async.wait_group 1;" ::: "memory")

__device__ __forceinline__ void ldsm_x4(uint32_t* r, uint32_t addr) {
    asm volatile("ldmatrix.sync.aligned.m8n8.x4.shared.b16 {%0,%1,%2,%3}, [%4];"
        : "=r"(r[0]), "=r"(r[1]), "=r"(r[2]), "=r"(r[3]) : "r"(addr));
}
__device__ __forceinline__ void ldsm_x4_t(uint32_t* r, uint32_t addr) {
    asm volatile("ldmatrix.sync.aligned.m8n8.x4.trans.shared.b16 {%0,%1,%2,%3}, [%4];"
        : "=r"(r[0]), "=r"(r[1]), "=r"(r[2]), "=r"(r[3]) : "r"(addr));
}

__device__ __forceinline__ void mma_fp16(float* d, const uint32_t* a,
                                         uint32_t b0, uint32_t b1) {
    asm volatile(
        "mma.sync.aligned.m16n8k16.row.col.f32.f16.f16.f32 "
        "{%0,%1,%2,%3}, {%4,%5,%6,%7}, {%8,%9}, {%0,%1,%2,%3};"
        : "+f"(d[0]), "+f"(d[1]), "+f"(d[2]), "+f"(d[3])
        : "r"(a[0]), "r"(a[1]), "r"(a[2]), "r"(a[3]), "r"(b0), "r"(b1));
}

// ---------------- conversion kernels ----------------
__device__ __forceinline__ void split1h(float v, __half& h, __half& l) {
    h = __float2half_rn(v);
    l = __float2half_rn(v - __half2float(h));
}

__global__ void split_half_kernel(const float* __restrict__ in,
                                  __half* __restrict__ hi,
                                  __half* __restrict__ lo, int n)
{
    int idx = (blockIdx.x * blockDim.x + threadIdx.x) * 4;
    if (idx >= n) return;
    float4 v = *reinterpret_cast<const float4*>(in + idx);
    __half h0, h1, h2, h3, l0, l1, l2, l3;
    split1h(v.x, h0, l0); split1h(v.y, h1, l1);
    split1h(v.z, h2, l2); split1h(v.w, h3, l3);
    *reinterpret_cast<__half2*>(hi + idx)     = __half2(h0, h1);
    *reinterpret_cast<__half2*>(hi + idx + 2) = __half2(h2, h3);
    *reinterpret_cast<__half2*>(lo + idx)     = __half2(l0, l1);
    *reinterpret_cast<__half2*>(lo + idx + 2) = __half2(l2, l3);
}

__global__ void transpose_half_kernel(const float* __restrict__ W,
                                      __half* __restrict__ t16, int K, int N)
{
    __shared__ float t[32][33];
    const int tx = threadIdx.x, ty = threadIdx.y;
    const int n0 = blockIdx.x * 32, k0 = blockIdx.y * 32;
#pragma unroll
    for (int j = ty; j < 32; j += 8)
        t[j][tx] = W[(size_t)(k0 + j) * N + n0 + tx];
    __syncthreads();
#pragma unroll
    for (int j = ty; j < 32; j += 8)
        t16[(size_t)(n0 + j) * K + k0 + tx] = __float2half_rn(t[tx][j]);
}

// ---------------- mma.sync fp16 2-term GEMM, 3-stage pipeline -------------
// C[M,N] = (Ah + Al)[M,K] @ B[N,K]^T + bias, fp32 acc.
// 3 cp.async stages, wait_group(1): each load has 2 chunk-times to land.
#define TS 40
#define TILE_B (128 * TS * 2)          // 10240 B
#define STAGE_B (3 * TILE_B)           // Ah, Al, B
#define NSTAGE 3
#define GEMM_SMEM (NSTAGE * STAGE_B)   // 92160 B

template <bool SPLIT_OUT>
__global__ __launch_bounds__(256) void gemm_mma_kernel(
    const __half* __restrict__ Ah, const __half* __restrict__ Al,
    const __half* __restrict__ B,
    const float* __restrict__ bias, float* __restrict__ C,
    __half* __restrict__ Ch, __half* __restrict__ Cl, int N)
{
    extern __shared__ char smem[];
    const uint32_t sbase = smem_u32(smem);
    const int tid = threadIdx.x;
    const int wid = tid >> 5, lane = tid & 31;
    const int m0 = blockIdx.y * 128, n0 = blockIdx.x * 128;
    const int wm = wid >> 2, wn = wid & 3;

    const __half* aHb = Ah + (size_t)m0 * KDIM;
    const __half* aLb = Al + (size_t)m0 * KDIM;
    const __half* bBb = B + (size_t)n0 * KDIM;

    float acc[4][4][4];
#pragma unroll
    for (int i = 0; i < 4; i++)
#pragma unroll
        for (int j = 0; j < 4; j++)
#pragma unroll
            for (int v = 0; v < 4; v++) acc[i][j][v] = 0.f;

    const int NC = KDIM / 32;  // 32

    auto issue = [&](int stage, int c) {
        const int k0 = c * 32;
        const uint32_t sb = sbase + stage * STAGE_B;
#pragma unroll
        for (int i = 0; i < 2; i++) {
            const int cid = tid + 256 * i;
            const int r = cid >> 2, q = cid & 3;
            const uint32_t so = (r * TS + q * 8) * 2;
            cp16(sb + so, aHb + (size_t)r * KDIM + k0 + q * 8);
            cp16(sb + TILE_B + so, aLb + (size_t)r * KDIM + k0 + q * 8);
            cp16(sb + 2 * TILE_B + so, bBb + (size_t)r * KDIM + k0 + q * 8);
        }
        CP_COMMIT();
    };

    issue(0, 0);
    issue(1, 1);

    int st = 0;
    for (int c = 0; c < NC; c++) {
        // stage c resident: with groups {c, c+1} possibly outstanding,
        // wait_group(1) retires group c; last iter drains fully.
        if (c + 1 < NC) { CP_WAIT1(); } else { CP_WAIT0(); }
        __syncthreads();   // all warps done reading stage (c-1)'s slot
        if (c + 2 < NC) {
            int ns = st + 2; if (ns >= NSTAGE) ns -= NSTAGE;
            issue(ns, c + 2);  // overwrites stage (c-1)'s slot: safe
        }

        const uint32_t sAh = sbase + st * STAGE_B;
        const uint32_t sAl = sAh + TILE_B;
        const uint32_t sB  = sAh + 2 * TILE_B;

        const int rowa = wm * 64 + (lane & 15);
        const int rowb = wn * 32 + (lane & 15);
        const int ko = (lane >> 4) * 8;

#pragma unroll
        for (int kt = 0; kt < 2; kt++) {
            const int k = kt * 16 + ko;
            uint32_t ah[4][4], al[4][4], bb[2][4];
#pragma unroll
            for (int mt = 0; mt < 4; mt++) {
                ldsm_x4(ah[mt], sAh + ((rowa + mt * 16) * TS + k) * 2);
                ldsm_x4(al[mt], sAl + ((rowa + mt * 16) * TS + k) * 2);
            }
#pragma unroll
            for (int nt = 0; nt < 2; nt++)
                ldsm_x4(bb[nt], sB + ((rowb + nt * 16) * TS + k) * 2);
            // term-major: all Ah*B, then all Al*B
#pragma unroll
            for (int mt = 0; mt < 4; mt++)
#pragma unroll
                for (int nt = 0; nt < 2; nt++)
#pragma unroll
                    for (int h = 0; h < 2; h++)
                        mma_fp16(acc[mt][nt * 2 + h], ah[mt],
                                 bb[nt][h], bb[nt][h + 2]);
#pragma unroll
            for (int mt = 0; mt < 4; mt++)
#pragma unroll
                for (int nt = 0; nt < 2; nt++)
#pragma unroll
                    for (int h = 0; h < 2; h++)
                        mma_fp16(acc[mt][nt * 2 + h], al[mt],
                                 bb[nt][h], bb[nt][h + 2]);
        }
        if (++st >= NSTAGE) st = 0;
    }

    // epilogue
    const int g = lane >> 2, tig = lane & 3;
#pragma unroll
    for (int mt = 0; mt < 4; mt++) {
#pragma unroll
        for (int n8 = 0; n8 < 4; n8++) {
            const int col = n0 + wn * 32 + n8 * 8 + tig * 2;
            const float2 bv = *reinterpret_cast<const float2*>(bias + col);
            const int row = m0 + wm * 64 + mt * 16 + g;
            float* d = acc[mt][n8];
            float2 o0 = make_float2(d[0] + bv.x, d[1] + bv.y);
            float2 o1 = make_float2(d[2] + bv.x, d[3] + bv.y);
            if constexpr (SPLIT_OUT) {
                __half h0, h1, l0, l1;
                split1h(o0.x, h0, l0); split1h(o0.y, h1, l1);
                *reinterpret_cast<__half2*>(Ch + (size_t)row * N + col) = __half2(h0, h1);
                *reinterpret_cast<__half2*>(Cl + (size_t)row * N + col) = __half2(l0, l1);
                split1h(o1.x, h0, l0); split1h(o1.y, h1, l1);
                *reinterpret_cast<__half2*>(Ch + (size_t)(row + 8) * N + col) = __half2(h0, h1);
                *reinterpret_cast<__half2*>(Cl + (size_t)(row + 8) * N + col) = __half2(l0, l1);
            } else {
                *reinterpret_cast<float2*>(C + (size_t)row * N + col) = o0;
                *reinterpret_cast<float2*>(C + (size_t)(row + 8) * N + col) = o1;
            }
        }
    }
}

// ---------------- mma.sync flash attention (causal), fp16 ----------------
// S = QhKh + QhKl + QlKh (3-term); PV = (Ph+Pl)*Vh (2-term). (validated R12)
#define AS 72
#define ATILE_B (64 * AS * 2)          // 9216 B
#define A_STAGE0 (2 * ATILE_B)         // Qh, Ql
#define A_STAGE_B (3 * ATILE_B)        // Kh, Kl, Vh
#define ATTN_SMEM (A_STAGE0 + 2 * A_STAGE_B)  // 73728 B

__global__ __launch_bounds__(128) void attn_mma_kernel(
    const __half* __restrict__ qkvh,
    const __half* __restrict__ qkvl,
    __half* __restrict__ yh, __half* __restrict__ yl)
{
    extern __shared__ char smem[];
    const uint32_t sb = smem_u32(smem);
    const int tid = threadIdx.x;
    const int wid = tid >> 5, lane = tid & 31;
    const int g = lane >> 2, tig = lane & 3;

    const int bh = blockIdx.y;
    const int b = bh >> 4, h = bh & 15;
    const int qt = (int)gridDim.x - 1 - (int)blockIdx.x;  // longest first
    const int q0 = qt * 64;

    const size_t rowbase = (size_t)b * SEQ * QKV_N + h * HD;
    const uint32_t sQh = sb, sQl = sb + ATILE_B;

    auto issueKV = [&](int stage, int kt) {
        const int k0 = kt * 64;
        const uint32_t sbK = sb + A_STAGE0 + stage * A_STAGE_B;
#pragma unroll
        for (int i = 0; i < 4; i++) {
            const int cid = tid + 128 * i;
            const int r = cid >> 3, q = cid & 7;
            const size_t gK = rowbase + (size_t)(k0 + r) * QKV_N + D_MODEL + q * 8;
            const size_t gV = gK + D_MODEL;
            const uint32_t so = (r * AS + q * 8) * 2;
            cp16(sbK + so, qkvh + gK);
            cp16(sbK + ATILE_B + so, qkvl + gK);
            cp16(sbK + 2 * ATILE_B + so, qkvh + gV);
        }
        CP_COMMIT();
    };

    {
#pragma unroll
        for (int i = 0; i < 4; i++) {
            const int cid = tid + 128 * i;
            const int r = cid >> 3, q = cid & 7;
            const size_t go = rowbase + (size_t)(q0 + r) * QKV_N + q * 8;
            cp16(sQh + (r * AS + q * 8) * 2, qkvh + go);
            cp16(sQl + (r * AS + q * 8) * 2, qkvl + go);
        }
    }
    issueKV(0, 0);

    float m[2], l[2], oacc[8][4];
    m[0] = m[1] = -INFINITY;
    l[0] = l[1] = 0.f;
#pragma unroll
    for (int t = 0; t < 8; t++)
#pragma unroll
        for (int v = 0; v < 4; v++) oacc[t][v] = 0.f;

    uint32_t qh[4][4], ql[4][4];
    bool qloaded = false;
    const float scale = 0.125f;
    const int rowa = wid * 16 + (lane & 15);
    const int ko = (lane >> 4) * 8;

    for (int kt = 0; kt <= qt; kt++) {
        CP_WAIT0();
        __syncthreads();
        if (kt < qt) issueKV((kt + 1) & 1, kt + 1);

        const uint32_t sK = sb + A_STAGE0 + (kt & 1) * A_STAGE_B;
        const uint32_t sKh = sK, sKl = sK + ATILE_B;
        const uint32_t sVh = sK + 2 * ATILE_B;

        if (!qloaded) {
#pragma unroll
            for (int kc = 0; kc < 4; kc++) {
                ldsm_x4(qh[kc], sQh + (rowa * AS + kc * 16 + ko) * 2);
                ldsm_x4(ql[kc], sQl + (rowa * AS + kc * 16 + ko) * 2);
            }
            qloaded = true;
        }

        // ---- S = Q K^T (3-term fp16, term-major per kc slice) ----
        float sacc[8][4];
#pragma unroll
        for (int t = 0; t < 8; t++)
#pragma unroll
            for (int v = 0; v < 4; v++) sacc[t][v] = 0.f;

#pragma unroll
        for (int kc = 0; kc < 4; kc++) {
            uint32_t kbh[4][4], kbl[4][4];
#pragma unroll
            for (int nt = 0; nt < 4; nt++) {
                const uint32_t ka = ((nt * 16 + (lane & 15)) * AS + kc * 16 + ko) * 2;
                ldsm_x4(kbh[nt], sKh + ka);
                ldsm_x4(kbl[nt], sKl + ka);
            }
#pragma unroll
            for (int nt = 0; nt < 4; nt++)
#pragma unroll
                for (int hh = 0; hh < 2; hh++)
                    mma_fp16(sacc[nt * 2 + hh], qh[kc],
                             kbh[nt][hh], kbh[nt][hh + 2]);
#pragma unroll
            for (int nt = 0; nt < 4; nt++)
#pragma unroll
                for (int hh = 0; hh < 2; hh++)
                    mma_fp16(sacc[nt * 2 + hh], qh[kc],
                             kbl[nt][hh], kbl[nt][hh + 2]);
#pragma unroll
            for (int nt = 0; nt < 4; nt++)
#pragma unroll
                for (int hh = 0; hh < 2; hh++)
                    mma_fp16(sacc[nt * 2 + hh], ql[kc],
                             kbh[nt][hh], kbh[nt][hh + 2]);
        }

        // scale + causal mask
        const int k0 = kt * 64;
        if (kt == qt) {
#pragma unroll
            for (int t = 0; t < 8; t++)
#pragma unroll
                for (int v = 0; v < 4; v++) {
                    const int kg = k0 + t * 8 + 2 * tig + (v & 1);
                    const int qg = q0 + wid * 16 + g + (v >> 1) * 8;
                    sacc[t][v] = (kg <= qg) ? sacc[t][v] * scale : -INFINITY;
                }
        } else {
#pragma unroll
            for (int t = 0; t < 8; t++)
#pragma unroll
                for (int v = 0; v < 4; v++) sacc[t][v] *= scale;
        }

        // online softmax
#pragma unroll
        for (int rh = 0; rh < 2; rh++) {
            float mt = -INFINITY;
#pragma unroll
            for (int t = 0; t < 8; t++)
                mt = fmaxf(mt, fmaxf(sacc[t][rh * 2], sacc[t][rh * 2 + 1]));
            mt = fmaxf(mt, __shfl_xor_sync(0xffffffffu, mt, 1));
            mt = fmaxf(mt, __shfl_xor_sync(0xffffffffu, mt, 2));
            const float mn = fmaxf(m[rh], mt);
            const float corr = __expf(m[rh] - mn);
            m[rh] = mn;
            float ps = 0.f;
#pragma unroll
            for (int t = 0; t < 8; t++) {
                float p0 = __expf(sacc[t][rh * 2] - mn);
                float p1 = __expf(sacc[t][rh * 2 + 1] - mn);
                sacc[t][rh * 2] = p0;
                sacc[t][rh * 2 + 1] = p1;
                ps += p0 + p1;
            }
            ps += __shfl_xor_sync(0xffffffffu, ps, 1);
            ps += __shfl_xor_sync(0xffffffffu, ps, 2);
            l[rh] = l[rh] * corr + ps;
#pragma unroll
            for (int t = 0; t < 8; t++) {
                oacc[t][rh * 2] *= corr;
                oacc[t][rh * 2 + 1] *= corr;
            }
        }

        // P -> fp16 hi/lo fragments (22-bit exact)
        uint32_t ph[8][2], pl[8][2];
#pragma unroll
        for (int t = 0; t < 8; t++)
#pragma unroll
            for (int rh = 0; rh < 2; rh++) {
                float2 f = make_float2(sacc[t][rh * 2], sacc[t][rh * 2 + 1]);
                __half2 h2 = __floats2half2_rn(f.x, f.y);
                float2 bk = __half22float2(h2);
                __half2 l2 = __floats2half2_rn(f.x - bk.x, f.y - bk.y);
                ph[t][rh] = *reinterpret_cast<uint32_t*>(&h2);
                pl[t][rh] = *reinterpret_cast<uint32_t*>(&l2);
            }

        // ---- O += P V (2-term, V single fp16, term-major per jc slice) ----
        const int vrow = ((lane >> 4) & 1) * 8 + (lane & 7);
        const int vcol = ((lane >> 3) & 1) * 8;
#pragma unroll
        for (int jc = 0; jc < 4; jc++) {
            uint32_t pa_h[4] = {ph[2 * jc][0], ph[2 * jc][1],
                                ph[2 * jc + 1][0], ph[2 * jc + 1][1]};
            uint32_t pa_l[4] = {pl[2 * jc][0], pl[2 * jc][1],
                                pl[2 * jc + 1][0], pl[2 * jc + 1][1]};
            uint32_t vbh[4][4];
#pragma unroll
            for (int dt = 0; dt < 4; dt++) {
                const uint32_t va = ((jc * 16 + vrow) * AS + dt * 16 + vcol) * 2;
                ldsm_x4_t(vbh[dt], sVh + va);
            }
#pragma unroll
            for (int dt = 0; dt < 4; dt++)
#pragma unroll
                for (int hh = 0; hh < 2; hh++)
                    mma_fp16(oacc[dt * 2 + hh], pa_h,
                             vbh[dt][hh], vbh[dt][hh + 2]);
#pragma unroll
            for (int dt = 0; dt < 4; dt++)
#pragma unroll
                for (int hh = 0; hh < 2; hh++)
                    mma_fp16(oacc[dt * 2 + hh], pa_l,
                             vbh[dt][hh], vbh[dt][hh + 2]);
        }
    }

    // epilogue: write y split fp16 hi/lo (feeds proj GEMM A-operand)
    const float inv0 = 1.f / l[0], inv1 = 1.f / l[1];
    const int row0 = q0 + wid * 16 + g;
#pragma unroll
    for (int t = 0; t < 8; t++) {
        const int col = h * HD + t * 8 + 2 * tig;
        const size_t o0i = ((size_t)b * SEQ + row0) * D_MODEL + col;
        const size_t o1i = ((size_t)b * SEQ + row0 + 8) * D_MODEL + col;
        __half h0, h1, l0, l1;
        split1h(oacc[t][0] * inv0, h0, l0);
        split1h(oacc[t][1] * inv0, h1, l1);
        *reinterpret_cast<__half2*>(yh + o0i) = __half2(h0, h1);
        *reinterpret_cast<__half2*>(yl + o0i) = __half2(l0, l1);
        split1h(oacc[t][2] * inv1, h0, l0);
        split1h(oacc[t][3] * inv1, h1, l1);
        *reinterpret_cast<__half2*>(yh + o1i) = __half2(h0, h1);
        *reinterpret_cast<__half2*>(yl + o1i) = __half2(l0, l1);
    }
}

// ---------------------------------------------------------------------------
extern "C" void kernel_launch(void* const* d_in, const int* in_sizes, int n_in,
                              void* d_out, int out_size)
{
    const float* x      = (const float*)d_in[0];
    const float* W_attn = (const float*)d_in[1];
    const float* b_attn = (const float*)d_in[2];
    const float* W_proj = (const float*)d_in[3];
    const float* b_proj = (const float*)d_in[4];
    float* out = (float*)d_out;

    __half *xh, *xl, *yh, *yl, *qvh, *qvl, *wat, *wpt;
    cudaGetSymbolAddress((void**)&xh, g_x_hi);
    cudaGetSymbolAddress((void**)&xl, g_x_lo);
    cudaGetSymbolAddress((void**)&yh, g_y_hi);
    cudaGetSymbolAddress((void**)&yl, g_y_lo);
    cudaGetSymbolAddress((void**)&qvh, g_qkv_hi);
    cudaGetSymbolAddress((void**)&qvl, g_qkv_lo);
    cudaGetSymbolAddress((void**)&wat, g_wat);
    cudaGetSymbolAddress((void**)&wpt, g_wpt);

    cudaFuncSetAttribute(gemm_mma_kernel<true>,
                         cudaFuncAttributeMaxDynamicSharedMemorySize, GEMM_SMEM);
    cudaFuncSetAttribute(gemm_mma_kernel<false>,
                         cudaFuncAttributeMaxDynamicSharedMemorySize, GEMM_SMEM);
    cudaFuncSetAttribute(attn_mma_kernel,
                         cudaFuncAttributeMaxDynamicSharedMemorySize, ATTN_SMEM);

    const int NX = M_TOTAL * KDIM;

    // prep: x -> fp16 hi/lo; weights -> fp16 transposed
    split_half_kernel<<<NX / (256 * 4), 256>>>(x, xh, xl, NX);
    transpose_half_kernel<<<dim3(QKV_N / 32, KDIM / 32), dim3(32, 8)>>>(
        W_attn, wat, KDIM, QKV_N);
    transpose_half_kernel<<<dim3(D_MODEL / 32, KDIM / 32), dim3(32, 8)>>>(
        W_proj, wpt, KDIM, D_MODEL);

    // 1) qkv = x @ W_attn + b_attn  -> fp16 hi/lo for attention
    gemm_mma_kernel<true><<<dim3(QKV_N / 128, M_TOTAL / 128), 256, GEMM_SMEM>>>(
        xh, xl, wat, b_attn, nullptr, qvh, qvl, QKV_N);

    // 2) flash attention (fp16: S 3-term, PV 2-term) -> y fp16 hi/lo
    attn_mma_kernel<<<dim3(SEQ / 64, BATCH * N_HEADS), 128, ATTN_SMEM>>>(
        qvh, qvl, yh, yl);

    // 3) out = y @ W_proj + b_proj (fp32 out)
    gemm_mma_kernel<false><<<dim3(D_MODEL / 128, M_TOTAL / 128), 256, GEMM_SMEM>>>(
        yh, yl, wpt, b_proj, out, nullptr, nullptr, D_MODEL);
}

// round 14
// speedup vs baseline: 1.1457x; 1.1457x over previous
#include <cuda_runtime.h>
#include <cuda_fp16.h>
#include <math.h>
#include <stdint.h>

#define D_MODEL 1024
#define N_HEADS 16
#define HD 64
#define BATCH 2
#define SEQ 2048
#define M_TOTAL (BATCH * SEQ)   // 4096
#define QKV_N (3 * D_MODEL)     // 3072
#define KDIM 1024

// ---------------- scratch (device globals; allocation-free) ----------------
__device__ __align__(256) __half g_x_hi[(size_t)M_TOTAL * KDIM];
__device__ __align__(256) __half g_x_lo[(size_t)M_TOTAL * KDIM];
__device__ __align__(256) __half g_y_hi[(size_t)M_TOTAL * KDIM];
__device__ __align__(256) __half g_qkv_hi[(size_t)M_TOTAL * QKV_N];
__device__ __align__(256) __half g_qkv_lo[(size_t)M_TOTAL * QKV_N];
__device__ __align__(256) __half g_wat[(size_t)QKV_N * KDIM];   // W_attn^T fp16
__device__ __align__(256) __half g_wpt[(size_t)D_MODEL * KDIM]; // W_proj^T fp16

// ---------------- helpers ----------------
__device__ __forceinline__ uint32_t smem_u32(const void* p) {
    uint32_t a;
    asm("{ .reg .u64 t; cvta.to.shared.u64 t, %1; cvt.u32.u64 %0, t; }"
        : "=r"(a) : "l"(p));
    return a;
}

__device__ __forceinline__ void cp16(uint32_t dst, const void* src) {
    asm volatile("cp.async.cg.shared.global [%0], [%1], 16;" :: "r"(dst), "l"(src));
}
#define CP_COMMIT() asm volatile("cp.async.commit_group;" ::: "memory")
#define CP_WAIT0()  asm volatile("cp.async.wait_group 0;" ::: "memory")
#define CP_WAIT1()  asm volatile("cp.async.wait_group 1;" ::: "memory")

__device__ __forceinline__ void ldsm_x4(uint32_t* r, uint32_t addr) {
    asm volatile("ldmatrix.sync.aligned.m8n8.x4.shared.b16 {%0,%1,%2,%3}, [%4];"
        : "=r"(r[0]), "=r"(r[1]), "=r"(r[2]), "=r"(r[3]) : "r"(addr));
}
__device__ __forceinline__ void ldsm_x4_t(uint32_t* r, uint32_t addr) {
    asm volatile("ldmatrix.sync.aligned.m8n8.x4.trans.shared.b16 {%0,%1,%2,%3}, [%4];"
        : "=r"(r[0]), "=r"(r[1]), "=r"(r[2]), "=r"(r[3]) : "r"(addr));
}

__device__ __forceinline__ void mma_fp16(float* d, const uint32_t* a,
                                         uint32_t b0, uint32_t b1) {
    asm volatile(
        "mma.sync.aligned.m16n8k16.row.col.f32.f16.f16.f32 "
        "{%0,%1,%2,%3}, {%4,%5,%6,%7}, {%8,%9}, {%0,%1,%2,%3};"
        : "+f"(d[0]), "+f"(d[1]), "+f"(d[2]), "+f"(d[3])
        : "r"(a[0]), "r"(a[1]), "r"(a[2]), "r"(a[3]), "r"(b0), "r"(b1));
}

// ---------------- conversion kernels ----------------
__device__ __forceinline__ void split1h(float v, __half& h, __half& l) {
    h = __float2half_rn(v);
    l = __float2half_rn(v - __half2float(h));
}

__global__ void split_half_kernel(const float* __restrict__ in,
                                  __half* __restrict__ hi,
                                  __half* __restrict__ lo, int n)
{
    int idx = (blockIdx.x * blockDim.x + threadIdx.x) * 4;
    if (idx >= n) return;
    float4 v = *reinterpret_cast<const float4*>(in + idx);
    __half h0, h1, h2, h3, l0, l1, l2, l3;
    split1h(v.x, h0, l0); split1h(v.y, h1, l1);
    split1h(v.z, h2, l2); split1h(v.w, h3, l3);
    *reinterpret_cast<__half2*>(hi + idx)     = __half2(h0, h1);
    *reinterpret_cast<__half2*>(hi + idx + 2) = __half2(h2, h3);
    *reinterpret_cast<__half2*>(lo + idx)     = __half2(l0, l1);
    *reinterpret_cast<__half2*>(lo + idx + 2) = __half2(l2, l3);
}

__global__ void transpose_half_kernel(const float* __restrict__ W,
                                      __half* __restrict__ t16, int K, int N)
{
    __shared__ float t[32][33];
    const int tx = threadIdx.x, ty = threadIdx.y;
    const int n0 = blockIdx.x * 32, k0 = blockIdx.y * 32;
#pragma unroll
    for (int j = ty; j < 32; j += 8)
        t[j][tx] = W[(size_t)(k0 + j) * N + n0 + tx];
    __syncthreads();
#pragma unroll
    for (int j = ty; j < 32; j += 8)
        t16[(size_t)(n0 + j) * K + k0 + tx] = __float2half_rn(t[tx][j]);
}

// ---------------- mma.sync fp16 GEMM, templated term count ---------------
// C[M,N] = (Ah [+ Al])[M,K] @ B[N,K]^T + bias, fp32 acc. 2-stage cp.async.
// NT=2: A hi+lo (22-bit exact). NT=1: A single fp16 (terminal outputs only).
#define TS 40
#define TILE_B (128 * TS * 2)          // 10240 B

template <int NT, bool SPLIT_OUT>
__global__ __launch_bounds__(256) void gemm_mma_kernel(
    const __half* __restrict__ Ah, const __half* __restrict__ Al,
    const __half* __restrict__ B,
    const float* __restrict__ bias, float* __restrict__ C,
    __half* __restrict__ Ch, __half* __restrict__ Cl, int N)
{
    constexpr uint32_t STAGE_B = (NT + 1) * TILE_B;
    extern __shared__ char smem[];
    const uint32_t sbase = smem_u32(smem);
    const int tid = threadIdx.x;
    const int wid = tid >> 5, lane = tid & 31;
    const int m0 = blockIdx.y * 128, n0 = blockIdx.x * 128;
    const int wm = wid >> 2, wn = wid & 3;

    const __half* aHb = Ah + (size_t)m0 * KDIM;
    const __half* aLb = (NT == 2) ? Al + (size_t)m0 * KDIM : nullptr;
    const __half* bBb = B + (size_t)n0 * KDIM;

    float acc[4][4][4];
#pragma unroll
    for (int i = 0; i < 4; i++)
#pragma unroll
        for (int j = 0; j < 4; j++)
#pragma unroll
            for (int v = 0; v < 4; v++) acc[i][j][v] = 0.f;

    const int NC = KDIM / 32;  // 32

    auto issue = [&](int stage, int c) {
        const int k0 = c * 32;
        const uint32_t sb = sbase + stage * STAGE_B;
#pragma unroll
        for (int i = 0; i < 2; i++) {
            const int cid = tid + 256 * i;
            const int r = cid >> 2, q = cid & 3;
            const uint32_t so = (r * TS + q * 8) * 2;
            cp16(sb + so, aHb + (size_t)r * KDIM + k0 + q * 8);
            if constexpr (NT == 2)
                cp16(sb + TILE_B + so, aLb + (size_t)r * KDIM + k0 + q * 8);
            cp16(sb + NT * TILE_B + so, bBb + (size_t)r * KDIM + k0 + q * 8);
        }
        CP_COMMIT();
    };

    issue(0, 0);

    for (int c = 0; c < NC; c++) {
        CP_WAIT0();
        __syncthreads();
        if (c + 1 < NC) issue((c + 1) & 1, c + 1);

        const int st = c & 1;
        const uint32_t sAh = sbase + st * STAGE_B;
        const uint32_t sAl = sAh + TILE_B;           // valid only if NT==2
        const uint32_t sB  = sAh + NT * TILE_B;

        const int rowa = wm * 64 + (lane & 15);
        const int rowb = wn * 32 + (lane & 15);
        const int ko = (lane >> 4) * 8;

#pragma unroll
        for (int kt = 0; kt < 2; kt++) {
            const int k = kt * 16 + ko;
            uint32_t ah[4][4], al[4][4], bb[2][4];
#pragma unroll
            for (int mt = 0; mt < 4; mt++) {
                ldsm_x4(ah[mt], sAh + ((rowa + mt * 16) * TS + k) * 2);
                if constexpr (NT == 2)
                    ldsm_x4(al[mt], sAl + ((rowa + mt * 16) * TS + k) * 2);
            }
#pragma unroll
            for (int nt = 0; nt < 2; nt++)
                ldsm_x4(bb[nt], sB + ((rowb + nt * 16) * TS + k) * 2);
            // term-major
#pragma unroll
            for (int mt = 0; mt < 4; mt++)
#pragma unroll
                for (int nt = 0; nt < 2; nt++)
#pragma unroll
                    for (int h = 0; h < 2; h++)
                        mma_fp16(acc[mt][nt * 2 + h], ah[mt],
                                 bb[nt][h], bb[nt][h + 2]);
            if constexpr (NT == 2) {
#pragma unroll
                for (int mt = 0; mt < 4; mt++)
#pragma unroll
                    for (int nt = 0; nt < 2; nt++)
#pragma unroll
                        for (int h = 0; h < 2; h++)
                            mma_fp16(acc[mt][nt * 2 + h], al[mt],
                                     bb[nt][h], bb[nt][h + 2]);
            }
        }
    }

    // epilogue
    const int g = lane >> 2, tig = lane & 3;
#pragma unroll
    for (int mt = 0; mt < 4; mt++) {
#pragma unroll
        for (int n8 = 0; n8 < 4; n8++) {
            const int col = n0 + wn * 32 + n8 * 8 + tig * 2;
            const float2 bv = *reinterpret_cast<const float2*>(bias + col);
            const int row = m0 + wm * 64 + mt * 16 + g;
            float* d = acc[mt][n8];
            float2 o0 = make_float2(d[0] + bv.x, d[1] + bv.y);
            float2 o1 = make_float2(d[2] + bv.x, d[3] + bv.y);
            if constexpr (SPLIT_OUT) {
                __half h0, h1, l0, l1;
                split1h(o0.x, h0, l0); split1h(o0.y, h1, l1);
                *reinterpret_cast<__half2*>(Ch + (size_t)row * N + col) = __half2(h0, h1);
                *reinterpret_cast<__half2*>(Cl + (size_t)row * N + col) = __half2(l0, l1);
                split1h(o1.x, h0, l0); split1h(o1.y, h1, l1);
                *reinterpret_cast<__half2*>(Ch + (size_t)(row + 8) * N + col) = __half2(h0, h1);
                *reinterpret_cast<__half2*>(Cl + (size_t)(row + 8) * N + col) = __half2(l0, l1);
            } else {
                *reinterpret_cast<float2*>(C + (size_t)row * N + col) = o0;
                *reinterpret_cast<float2*>(C + (size_t)(row + 8) * N + col) = o1;
            }
        }
    }
}

#define GEMM_SMEM_2T (2 * 3 * TILE_B)  // 61440
#define GEMM_SMEM_1T (2 * 2 * TILE_B)  // 40960

// ---------------- mma.sync flash attention (causal), fp16 ----------------
// S = QhKh + QlKh (2-term: Q 22-bit, K single fp16).
// PV = (Ph+Pl)*Vh (2-term: P 22-bit, V single fp16).
// K/V: 2 cp.async streams; smem 54KB. Output y single fp16 (feeds 1-term proj).
#define AS 72
#define ATILE_B (64 * AS * 2)          // 9216 B
#define A_STAGE0 (2 * ATILE_B)         // Qh, Ql
#define A_STAGE_B (2 * ATILE_B)        // Kh, Vh
#define ATTN_SMEM (A_STAGE0 + 2 * A_STAGE_B)  // 55296 B

__global__ __launch_bounds__(128) void attn_mma_kernel(
    const __half* __restrict__ qkvh,
    const __half* __restrict__ qkvl,
    __half* __restrict__ yh)
{
    extern __shared__ char smem[];
    const uint32_t sb = smem_u32(smem);
    const int tid = threadIdx.x;
    const int wid = tid >> 5, lane = tid & 31;
    const int g = lane >> 2, tig = lane & 3;

    const int bh = blockIdx.y;
    const int b = bh >> 4, h = bh & 15;
    const int qt = (int)gridDim.x - 1 - (int)blockIdx.x;  // longest first
    const int q0 = qt * 64;

    const size_t rowbase = (size_t)b * SEQ * QKV_N + h * HD;
    const uint32_t sQh = sb, sQl = sb + ATILE_B;

    auto issueKV = [&](int stage, int kt) {
        const int k0 = kt * 64;
        const uint32_t sbK = sb + A_STAGE0 + stage * A_STAGE_B;
#pragma unroll
        for (int i = 0; i < 4; i++) {
            const int cid = tid + 128 * i;
            const int r = cid >> 3, q = cid & 7;
            const size_t gK = rowbase + (size_t)(k0 + r) * QKV_N + D_MODEL + q * 8;
            const size_t gV = gK + D_MODEL;
            const uint32_t so = (r * AS + q * 8) * 2;
            cp16(sbK + so, qkvh + gK);
            cp16(sbK + ATILE_B + so, qkvh + gV);
        }
        CP_COMMIT();
    };

    {
#pragma unroll
        for (int i = 0; i < 4; i++) {
            const int cid = tid + 128 * i;
            const int r = cid >> 3, q = cid & 7;
            const size_t go = rowbase + (size_t)(q0 + r) * QKV_N + q * 8;
            cp16(sQh + (r * AS + q * 8) * 2, qkvh + go);
            cp16(sQl + (r * AS + q * 8) * 2, qkvl + go);
        }
    }
    issueKV(0, 0);

    float m[2], l[2], oacc[8][4];
    m[0] = m[1] = -INFINITY;
    l[0] = l[1] = 0.f;
#pragma unroll
    for (int t = 0; t < 8; t++)
#pragma unroll
        for (int v = 0; v < 4; v++) oacc[t][v] = 0.f;

    uint32_t qh[4][4], ql[4][4];
    bool qloaded = false;
    const float scale = 0.125f;
    const int rowa = wid * 16 + (lane & 15);
    const int ko = (lane >> 4) * 8;

    for (int kt = 0; kt <= qt; kt++) {
        CP_WAIT0();
        __syncthreads();
        if (kt < qt) issueKV((kt + 1) & 1, kt + 1);

        const uint32_t sK = sb + A_STAGE0 + (kt & 1) * A_STAGE_B;
        const uint32_t sKh = sK;
        const uint32_t sVh = sK + ATILE_B;

        if (!qloaded) {
#pragma unroll
            for (int kc = 0; kc < 4; kc++) {
                ldsm_x4(qh[kc], sQh + (rowa * AS + kc * 16 + ko) * 2);
                ldsm_x4(ql[kc], sQl + (rowa * AS + kc * 16 + ko) * 2);
            }
            qloaded = true;
        }

        // ---- S = Q K^T (2-term: QhKh + QlKh), term-major per kc slice ----
        float sacc[8][4];
#pragma unroll
        for (int t = 0; t < 8; t++)
#pragma unroll
            for (int v = 0; v < 4; v++) sacc[t][v] = 0.f;

#pragma unroll
        for (int kc = 0; kc < 4; kc++) {
            uint32_t kbh[4][4];
#pragma unroll
            for (int nt = 0; nt < 4; nt++) {
                const uint32_t ka = ((nt * 16 + (lane & 15)) * AS + kc * 16 + ko) * 2;
                ldsm_x4(kbh[nt], sKh + ka);
            }
#pragma unroll
            for (int nt = 0; nt < 4; nt++)
#pragma unroll
                for (int hh = 0; hh < 2; hh++)
                    mma_fp16(sacc[nt * 2 + hh], qh[kc],
                             kbh[nt][hh], kbh[nt][hh + 2]);
#pragma unroll
            for (int nt = 0; nt < 4; nt++)
#pragma unroll
                for (int hh = 0; hh < 2; hh++)
                    mma_fp16(sacc[nt * 2 + hh], ql[kc],
                             kbh[nt][hh], kbh[nt][hh + 2]);
        }

        // scale + causal mask
        const int k0 = kt * 64;
        if (kt == qt) {
#pragma unroll
            for (int t = 0; t < 8; t++)
#pragma unroll
                for (int v = 0; v < 4; v++) {
                    const int kg = k0 + t * 8 + 2 * tig + (v & 1);
                    const int qg = q0 + wid * 16 + g + (v >> 1) * 8;
                    sacc[t][v] = (kg <= qg) ? sacc[t][v] * scale : -INFINITY;
                }
        } else {
#pragma unroll
            for (int t = 0; t < 8; t++)
#pragma unroll
                for (int v = 0; v < 4; v++) sacc[t][v] *= scale;
        }

        // online softmax
#pragma unroll
        for (int rh = 0; rh < 2; rh++) {
            float mt = -INFINITY;
#pragma unroll
            for (int t = 0; t < 8; t++)
                mt = fmaxf(mt, fmaxf(sacc[t][rh * 2], sacc[t][rh * 2 + 1]));
            mt = fmaxf(mt, __shfl_xor_sync(0xffffffffu, mt, 1));
            mt = fmaxf(mt, __shfl_xor_sync(0xffffffffu, mt, 2));
            const float mn = fmaxf(m[rh], mt);
            const float corr = __expf(m[rh] - mn);
            m[rh] = mn;
            float ps = 0.f;
#pragma unroll
            for (int t = 0; t < 8; t++) {
                float p0 = __expf(sacc[t][rh * 2] - mn);
                float p1 = __expf(sacc[t][rh * 2 + 1] - mn);
                sacc[t][rh * 2] = p0;
                sacc[t][rh * 2 + 1] = p1;
                ps += p0 + p1;
            }
            ps += __shfl_xor_sync(0xffffffffu, ps, 1);
            ps += __shfl_xor_sync(0xffffffffu, ps, 2);
            l[rh] = l[rh] * corr + ps;
#pragma unroll
            for (int t = 0; t < 8; t++) {
                oacc[t][rh * 2] *= corr;
                oacc[t][rh * 2 + 1] *= corr;
            }
        }

        // P -> fp16 hi/lo fragments (22-bit exact)
        uint32_t ph[8][2], pl[8][2];
#pragma unroll
        for (int t = 0; t < 8; t++)
#pragma unroll
            for (int rh = 0; rh < 2; rh++) {
                float2 f = make_float2(sacc[t][rh * 2], sacc[t][rh * 2 + 1]);
                __half2 h2 = __floats2half2_rn(f.x, f.y);
                float2 bk = __half22float2(h2);
                __half2 l2 = __floats2half2_rn(f.x - bk.x, f.y - bk.y);
                ph[t][rh] = *reinterpret_cast<uint32_t*>(&h2);
                pl[t][rh] = *reinterpret_cast<uint32_t*>(&l2);
            }

        // ---- O += P V (2-term: (Ph+Pl)*Vh), term-major per jc slice ----
        const int vrow = ((lane >> 4) & 1) * 8 + (lane & 7);
        const int vcol = ((lane >> 3) & 1) * 8;
#pragma unroll
        for (int jc = 0; jc < 4; jc++) {
            uint32_t pa_h[4] = {ph[2 * jc][0], ph[2 * jc][1],
                                ph[2 * jc + 1][0], ph[2 * jc + 1][1]};
            uint32_t pa_l[4] = {pl[2 * jc][0], pl[2 * jc][1],
                                pl[2 * jc + 1][0], pl[2 * jc + 1][1]};
            uint32_t vbh[4][4];
#pragma unroll
            for (int dt = 0; dt < 4; dt++) {
                const uint32_t va = ((jc * 16 + vrow) * AS + dt * 16 + vcol) * 2;
                ldsm_x4_t(vbh[dt], sVh + va);
            }
#pragma unroll
            for (int dt = 0; dt < 4; dt++)
#pragma unroll
                for (int hh = 0; hh < 2; hh++)
                    mma_fp16(oacc[dt * 2 + hh], pa_h,
                             vbh[dt][hh], vbh[dt][hh + 2]);
#pragma unroll
            for (int dt = 0; dt < 4; dt++)
#pragma unroll
                for (int hh = 0; hh < 2; hh++)
                    mma_fp16(oacc[dt * 2 + hh], pa_l,
                             vbh[dt][hh], vbh[dt][hh + 2]);
        }
    }

    // epilogue: write y single fp16 (feeds 1-term proj GEMM)
    const float inv0 = 1.f / l[0], inv1 = 1.f / l[1];
    const int row0 = q0 + wid * 16 + g;
#pragma unroll
    for (int t = 0; t < 8; t++) {
        const int col = h * HD + t * 8 + 2 * tig;
        const size_t o0i = ((size_t)b * SEQ + row0) * D_MODEL + col;
        const size_t o1i = ((size_t)b * SEQ + row0 + 8) * D_MODEL + col;
        __half2 h0 = __floats2half2_rn(oacc[t][0] * inv0, oacc[t][1] * inv0);
        __half2 h1 = __floats2half2_rn(oacc[t][2] * inv1, oacc[t][3] * inv1);
        *reinterpret_cast<__half2*>(yh + o0i) = h0;
        *reinterpret_cast<__half2*>(yh + o1i) = h1;
    }
}

// ---------------------------------------------------------------------------
extern "C" void kernel_launch(void* const* d_in, const int* in_sizes, int n_in,
                              void* d_out, int out_size)
{
    const float* x      = (const float*)d_in[0];
    const float* W_attn = (const float*)d_in[1];
    const float* b_attn = (const float*)d_in[2];
    const float* W_proj = (const float*)d_in[3];
    const float* b_proj = (const float*)d_in[4];
    float* out = (float*)d_out;

    __half *xh, *xl, *yh, *qvh, *qvl, *wat, *wpt;
    cudaGetSymbolAddress((void**)&xh, g_x_hi);
    cudaGetSymbolAddress((void**)&xl, g_x_lo);
    cudaGetSymbolAddress((void**)&yh, g_y_hi);
    cudaGetSymbolAddress((void**)&qvh, g_qkv_hi);
    cudaGetSymbolAddress((void**)&qvl, g_qkv_lo);
    cudaGetSymbolAddress((void**)&wat, g_wat);
    cudaGetSymbolAddress((void**)&wpt, g_wpt);

    cudaFuncSetAttribute((const void*)gemm_mma_kernel<2, true>,
                         cudaFuncAttributeMaxDynamicSharedMemorySize, GEMM_SMEM_2T);
    cudaFuncSetAttribute((const void*)gemm_mma_kernel<1, false>,
                         cudaFuncAttributeMaxDynamicSharedMemorySize, GEMM_SMEM_1T);
    cudaFuncSetAttribute((const void*)attn_mma_kernel,
                         cudaFuncAttributeMaxDynamicSharedMemorySize, ATTN_SMEM);

    const int NX = M_TOTAL * KDIM;

    // prep: x -> fp16 hi/lo; weights -> fp16 transposed
    split_half_kernel<<<NX / (256 * 4), 256>>>(x, xh, xl, NX);
    transpose_half_kernel<<<dim3(QKV_N / 32, KDIM / 32), dim3(32, 8)>>>(
        W_attn, wat, KDIM, QKV_N);
    transpose_half_kernel<<<dim3(D_MODEL / 32, KDIM / 32), dim3(32, 8)>>>(
        W_proj, wpt, KDIM, D_MODEL);

    // 1) qkv = x @ W_attn + b_attn (2-term, 22-bit A) -> fp16 hi/lo
    gemm_mma_kernel<2, true><<<dim3(QKV_N / 128, M_TOTAL / 128), 256, GEMM_SMEM_2T>>>(
        xh, xl, wat, b_attn, nullptr, qvh, qvl, QKV_N);

    // 2) flash attention (S 2-term, PV 2-term) -> y single fp16
    attn_mma_kernel<<<dim3(SEQ / 64, BATCH * N_HEADS), 128, ATTN_SMEM>>>(
        qvh, qvl, yh);

    // 3) out = y @ W_proj + b_proj (1-term: terminal output, no amplification)
    gemm_mma_kernel<1, false><<<dim3(D_MODEL / 128, M_TOTAL / 128), 256, GEMM_SMEM_1T>>>(
        yh, nullptr, wpt, b_proj, out, nullptr, nullptr, D_MODEL);
}

// round 16
// speedup vs baseline: 1.4319x; 1.2498x over previous
#include <cuda_runtime.h>
#include <cuda_fp16.h>
#include <math.h>
#include <stdint.h>

#define D_MODEL 1024
#define N_HEADS 16
#define HD 64
#define BATCH 2
#define SEQ 2048
#define M_TOTAL (BATCH * SEQ)   // 4096
#define QKV_N (3 * D_MODEL)     // 3072
#define KDIM 1024

// ---------------- scratch (device globals; allocation-free) ----------------
__device__ __align__(256) __half g_x_hi[(size_t)M_TOTAL * KDIM];
__device__ __align__(256) __half g_y_hi[(size_t)M_TOTAL * KDIM];
__device__ __align__(256) __half g_qkv_hi[(size_t)M_TOTAL * QKV_N];
__device__ __align__(256) __half g_qkv_lo[(size_t)M_TOTAL * QKV_N];
__device__ __align__(256) __half g_wat[(size_t)QKV_N * KDIM];   // W_attn^T fp16
__device__ __align__(256) __half g_wpt[(size_t)D_MODEL * KDIM]; // W_proj^T fp16

// ---------------- helpers ----------------
__device__ __forceinline__ uint32_t smem_u32(const void* p) {
    uint32_t a;
    asm("{ .reg .u64 t; cvta.to.shared.u64 t, %1; cvt.u32.u64 %0, t; }"
        : "=r"(a) : "l"(p));
    return a;
}

__device__ __forceinline__ void cp16(uint32_t dst, const void* src) {
    asm volatile("cp.async.cg.shared.global [%0], [%1], 16;" :: "r"(dst), "l"(src));
}
#define CP_COMMIT() asm volatile("cp.async.commit_group;" ::: "memory")
#define CP_WAIT0()  asm volatile("cp.async.wait_group 0;" ::: "memory")

__device__ __forceinline__ void ldsm_x4(uint32_t* r, uint32_t addr) {
    asm volatile("ldmatrix.sync.aligned.m8n8.x4.shared.b16 {%0,%1,%2,%3}, [%4];"
        : "=r"(r[0]), "=r"(r[1]), "=r"(r[2]), "=r"(r[3]) : "r"(addr));
}
__device__ __forceinline__ void ldsm_x4_t(uint32_t* r, uint32_t addr) {
    asm volatile("ldmatrix.sync.aligned.m8n8.x4.trans.shared.b16 {%0,%1,%2,%3}, [%4];"
        : "=r"(r[0]), "=r"(r[1]), "=r"(r[2]), "=r"(r[3]) : "r"(addr));
}

__device__ __forceinline__ void mma_fp16(float* d, const uint32_t* a,
                                         uint32_t b0, uint32_t b1) {
    asm volatile(
        "mma.sync.aligned.m16n8k16.row.col.f32.f16.f16.f32 "
        "{%0,%1,%2,%3}, {%4,%5,%6,%7}, {%8,%9}, {%0,%1,%2,%3};"
        : "+f"(d[0]), "+f"(d[1]), "+f"(d[2]), "+f"(d[3])
        : "r"(a[0]), "r"(a[1]), "r"(a[2]), "r"(a[3]), "r"(b0), "r"(b1));
}

// ---------------- conversion kernels ----------------
__device__ __forceinline__ void split1h(float v, __half& h, __half& l) {
    h = __float2half_rn(v);
    l = __float2half_rn(v - __half2float(h));
}

// float -> single fp16
__global__ void convert_half_kernel(const float* __restrict__ in,
                                    __half* __restrict__ hi, int n)
{
    int idx = (blockIdx.x * blockDim.x + threadIdx.x) * 4;
    if (idx >= n) return;
    float4 v = *reinterpret_cast<const float4*>(in + idx);
    *reinterpret_cast<__half2*>(hi + idx)     = __floats2half2_rn(v.x, v.y);
    *reinterpret_cast<__half2*>(hi + idx + 2) = __floats2half2_rn(v.z, v.w);
}

__global__ void transpose_half_kernel(const float* __restrict__ W,
                                      __half* __restrict__ t16, int K, int N)
{
    __shared__ float t[32][33];
    const int tx = threadIdx.x, ty = threadIdx.y;
    const int n0 = blockIdx.x * 32, k0 = blockIdx.y * 32;
#pragma unroll
    for (int j = ty; j < 32; j += 8)
        t[j][tx] = W[(size_t)(k0 + j) * N + n0 + tx];
    __syncthreads();
#pragma unroll
    for (int j = ty; j < 32; j += 8)
        t16[(size_t)(n0 + j) * K + k0 + tx] = __float2half_rn(t[tx][j]);
}

// ---------------- mma.sync fp16 GEMM, templated term count ---------------
// C[M,N] = (Ah [+ Al])[M,K] @ B[N,K]^T + bias, fp32 acc. 2-stage cp.async.
#define TS 40
#define TILE_B (128 * TS * 2)          // 10240 B

template <int NT, bool SPLIT_OUT>
__global__ __launch_bounds__(256) void gemm_mma_kernel(
    const __half* __restrict__ Ah, const __half* __restrict__ Al,
    const __half* __restrict__ B,
    const float* __restrict__ bias, float* __restrict__ C,
    __half* __restrict__ Ch, __half* __restrict__ Cl, int N)
{
    constexpr uint32_t STAGE_B = (NT + 1) * TILE_B;
    extern __shared__ char smem[];
    const uint32_t sbase = smem_u32(smem);
    const int tid = threadIdx.x;
    const int wid = tid >> 5, lane = tid & 31;
    const int m0 = blockIdx.y * 128, n0 = blockIdx.x * 128;
    const int wm = wid >> 2, wn = wid & 3;

    const __half* aHb = Ah + (size_t)m0 * KDIM;
    const __half* aLb = (NT == 2) ? Al + (size_t)m0 * KDIM : nullptr;
    const __half* bBb = B + (size_t)n0 * KDIM;

    float acc[4][4][4];
#pragma unroll
    for (int i = 0; i < 4; i++)
#pragma unroll
        for (int j = 0; j < 4; j++)
#pragma unroll
            for (int v = 0; v < 4; v++) acc[i][j][v] = 0.f;

    const int NC = KDIM / 32;  // 32

    auto issue = [&](int stage, int c) {
        const int k0 = c * 32;
        const uint32_t sb = sbase + stage * STAGE_B;
#pragma unroll
        for (int i = 0; i < 2; i++) {
            const int cid = tid + 256 * i;
            const int r = cid >> 2, q = cid & 3;
            const uint32_t so = (r * TS + q * 8) * 2;
            cp16(sb + so, aHb + (size_t)r * KDIM + k0 + q * 8);
            if constexpr (NT == 2)
                cp16(sb + TILE_B + so, aLb + (size_t)r * KDIM + k0 + q * 8);
            cp16(sb + NT * TILE_B + so, bBb + (size_t)r * KDIM + k0 + q * 8);
        }
        CP_COMMIT();
    };

    issue(0, 0);

    for (int c = 0; c < NC; c++) {
        CP_WAIT0();
        __syncthreads();
        if (c + 1 < NC) issue((c + 1) & 1, c + 1);

        const int st = c & 1;
        const uint32_t sAh = sbase + st * STAGE_B;
        const uint32_t sAl = sAh + TILE_B;           // valid only if NT==2
        const uint32_t sB  = sAh + NT * TILE_B;

        const int rowa = wm * 64 + (lane & 15);
        const int rowb = wn * 32 + (lane & 15);
        const int ko = (lane >> 4) * 8;

#pragma unroll
        for (int kt = 0; kt < 2; kt++) {
            const int k = kt * 16 + ko;
            uint32_t ah[4][4], al[4][4], bb[2][4];
#pragma unroll
            for (int mt = 0; mt < 4; mt++) {
                ldsm_x4(ah[mt], sAh + ((rowa + mt * 16) * TS + k) * 2);
                if constexpr (NT == 2)
                    ldsm_x4(al[mt], sAl + ((rowa + mt * 16) * TS + k) * 2);
            }
#pragma unroll
            for (int nt = 0; nt < 2; nt++)
                ldsm_x4(bb[nt], sB + ((rowb + nt * 16) * TS + k) * 2);
            // term-major
#pragma unroll
            for (int mt = 0; mt < 4; mt++)
#pragma unroll
                for (int nt = 0; nt < 2; nt++)
#pragma unroll
                    for (int h = 0; h < 2; h++)
                        mma_fp16(acc[mt][nt * 2 + h], ah[mt],
                                 bb[nt][h], bb[nt][h + 2]);
            if constexpr (NT == 2) {
#pragma unroll
                for (int mt = 0; mt < 4; mt++)
#pragma unroll
                    for (int nt = 0; nt < 2; nt++)
#pragma unroll
                        for (int h = 0; h < 2; h++)
                            mma_fp16(acc[mt][nt * 2 + h], al[mt],
                                     bb[nt][h], bb[nt][h + 2]);
            }
        }
    }

    // epilogue
    const int g = lane >> 2, tig = lane & 3;
#pragma unroll
    for (int mt = 0; mt < 4; mt++) {
#pragma unroll
        for (int n8 = 0; n8 < 4; n8++) {
            const int col = n0 + wn * 32 + n8 * 8 + tig * 2;
            const float2 bv = *reinterpret_cast<const float2*>(bias + col);
            const int row = m0 + wm * 64 + mt * 16 + g;
            float* d = acc[mt][n8];
            float2 o0 = make_float2(d[0] + bv.x, d[1] + bv.y);
            float2 o1 = make_float2(d[2] + bv.x, d[3] + bv.y);
            if constexpr (SPLIT_OUT) {
                __half h0, h1, l0, l1;
                split1h(o0.x, h0, l0); split1h(o0.y, h1, l1);
                *reinterpret_cast<__half2*>(Ch + (size_t)row * N + col) = __half2(h0, h1);
                *reinterpret_cast<__half2*>(Cl + (size_t)row * N + col) = __half2(l0, l1);
                split1h(o1.x, h0, l0); split1h(o1.y, h1, l1);
                *reinterpret_cast<__half2*>(Ch + (size_t)(row + 8) * N + col) = __half2(h0, h1);
                *reinterpret_cast<__half2*>(Cl + (size_t)(row + 8) * N + col) = __half2(l0, l1);
            } else {
                *reinterpret_cast<float2*>(C + (size_t)row * N + col) = o0;
                *reinterpret_cast<float2*>(C + (size_t)(row + 8) * N + col) = o1;
            }
        }
    }
}

#define GEMM_SMEM_2T (2 * 3 * TILE_B)  // 61440
#define GEMM_SMEM_1T (2 * 2 * TILE_B)  // 40960

// ---------------- mma.sync flash attention (causal), fp16 ----------------
// S = QhKh + QlKh (2-term); PV = (Ph+Pl)*Vh (2-term). (validated R14)
#define AS 72
#define ATILE_B (64 * AS * 2)          // 9216 B
#define A_STAGE0 (2 * ATILE_B)         // Qh, Ql
#define A_STAGE_B (2 * ATILE_B)        // Kh, Vh
#define ATTN_SMEM (A_STAGE0 + 2 * A_STAGE_B)  // 55296 B

__global__ __launch_bounds__(128) void attn_mma_kernel(
    const __half* __restrict__ qkvh,
    const __half* __restrict__ qkvl,
    __half* __restrict__ yh)
{
    extern __shared__ char smem[];
    const uint32_t sb = smem_u32(smem);
    const int tid = threadIdx.x;
    const int wid = tid >> 5, lane = tid & 31;
    const int g = lane >> 2, tig = lane & 3;

    const int bh = blockIdx.y;
    const int b = bh >> 4, h = bh & 15;
    const int qt = (int)gridDim.x - 1 - (int)blockIdx.x;  // longest first
    const int q0 = qt * 64;

    const size_t rowbase = (size_t)b * SEQ * QKV_N + h * HD;
    const uint32_t sQh = sb, sQl = sb + ATILE_B;

    auto issueKV = [&](int stage, int kt) {
        const int k0 = kt * 64;
        const uint32_t sbK = sb + A_STAGE0 + stage * A_STAGE_B;
#pragma unroll
        for (int i = 0; i < 4; i++) {
            const int cid = tid + 128 * i;
            const int r = cid >> 3, q = cid & 7;
            const size_t gK = rowbase + (size_t)(k0 + r) * QKV_N + D_MODEL + q * 8;
            const size_t gV = gK + D_MODEL;
            const uint32_t so = (r * AS + q * 8) * 2;
            cp16(sbK + so, qkvh + gK);
            cp16(sbK + ATILE_B + so, qkvh + gV);
        }
        CP_COMMIT();
    };

    {
#pragma unroll
        for (int i = 0; i < 4; i++) {
            const int cid = tid + 128 * i;
            const int r = cid >> 3, q = cid & 7;
            const size_t go = rowbase + (size_t)(q0 + r) * QKV_N + q * 8;
            cp16(sQh + (r * AS + q * 8) * 2, qkvh + go);
            cp16(sQl + (r * AS + q * 8) * 2, qkvl + go);
        }
    }
    issueKV(0, 0);

    float m[2], l[2], oacc[8][4];
    m[0] = m[1] = -INFINITY;
    l[0] = l[1] = 0.f;
#pragma unroll
    for (int t = 0; t < 8; t++)
#pragma unroll
        for (int v = 0; v < 4; v++) oacc[t][v] = 0.f;

    uint32_t qh[4][4], ql[4][4];
    bool qloaded = false;
    const float scale = 0.125f;
    const int rowa = wid * 16 + (lane & 15);
    const int ko = (lane >> 4) * 8;

    for (int kt = 0; kt <= qt; kt++) {
        CP_WAIT0();
        __syncthreads();
        if (kt < qt) issueKV((kt + 1) & 1, kt + 1);

        const uint32_t sK = sb + A_STAGE0 + (kt & 1) * A_STAGE_B;
        const uint32_t sKh = sK;
        const uint32_t sVh = sK + ATILE_B;

        if (!qloaded) {
#pragma unroll
            for (int kc = 0; kc < 4; kc++) {
                ldsm_x4(qh[kc], sQh + (rowa * AS + kc * 16 + ko) * 2);
                ldsm_x4(ql[kc], sQl + (rowa * AS + kc * 16 + ko) * 2);
            }
            qloaded = true;
        }

        // ---- S = Q K^T (2-term: QhKh + QlKh), term-major per kc slice ----
        float sacc[8][4];
#pragma unroll
        for (int t = 0; t < 8; t++)
#pragma unroll
            for (int v = 0; v < 4; v++) sacc[t][v] = 0.f;

#pragma unroll
        for (int kc = 0; kc < 4; kc++) {
            uint32_t kbh[4][4];
#pragma unroll
            for (int nt = 0; nt < 4; nt++) {
                const uint32_t ka = ((nt * 16 + (lane & 15)) * AS + kc * 16 + ko) * 2;
                ldsm_x4(kbh[nt], sKh + ka);
            }
#pragma unroll
            for (int nt = 0; nt < 4; nt++)
#pragma unroll
                for (int hh = 0; hh < 2; hh++)
                    mma_fp16(sacc[nt * 2 + hh], qh[kc],
                             kbh[nt][hh], kbh[nt][hh + 2]);
#pragma unroll
            for (int nt = 0; nt < 4; nt++)
#pragma unroll
                for (int hh = 0; hh < 2; hh++)
                    mma_fp16(sacc[nt * 2 + hh], ql[kc],
                             kbh[nt][hh], kbh[nt][hh + 2]);
        }

        // scale + causal mask
        const int k0 = kt * 64;
        if (kt == qt) {
#pragma unroll
            for (int t = 0; t < 8; t++)
#pragma unroll
                for (int v = 0; v < 4; v++) {
                    const int kg = k0 + t * 8 + 2 * tig + (v & 1);
                    const int qg = q0 + wid * 16 + g + (v >> 1) * 8;
                    sacc[t][v] = (kg <= qg) ? sacc[t][v] * scale : -INFINITY;
                }
        } else {
#pragma unroll
            for (int t = 0; t < 8; t++)
#pragma unroll
                for (int v = 0; v < 4; v++) sacc[t][v] *= scale;
        }

        // online softmax
#pragma unroll
        for (int rh = 0; rh < 2; rh++) {
            float mt = -INFINITY;
#pragma unroll
            for (int t = 0; t < 8; t++)
                mt = fmaxf(mt, fmaxf(sacc[t][rh * 2], sacc[t][rh * 2 + 1]));
            mt = fmaxf(mt, __shfl_xor_sync(0xffffffffu, mt, 1));
            mt = fmaxf(mt, __shfl_xor_sync(0xffffffffu, mt, 2));
            const float mn = fmaxf(m[rh], mt);
            const float corr = __expf(m[rh] - mn);
            m[rh] = mn;
            float ps = 0.f;
#pragma unroll
            for (int t = 0; t < 8; t++) {
                float p0 = __expf(sacc[t][rh * 2] - mn);
                float p1 = __expf(sacc[t][rh * 2 + 1] - mn);
                sacc[t][rh * 2] = p0;
                sacc[t][rh * 2 + 1] = p1;
                ps += p0 + p1;
            }
            ps += __shfl_xor_sync(0xffffffffu, ps, 1);
            ps += __shfl_xor_sync(0xffffffffu, ps, 2);
            l[rh] = l[rh] * corr + ps;
#pragma unroll
            for (int t = 0; t < 8; t++) {
                oacc[t][rh * 2] *= corr;
                oacc[t][rh * 2 + 1] *= corr;
            }
        }

        // P -> fp16 hi/lo fragments (22-bit exact)
        uint32_t ph[8][2], pl[8][2];
#pragma unroll
        for (int t = 0; t < 8; t++)
#pragma unroll
            for (int rh = 0; rh < 2; rh++) {
                float2 f = make_float2(sacc[t][rh * 2], sacc[t][rh * 2 + 1]);
                __half2 h2 = __floats2half2_rn(f.x, f.y);
                float2 bk = __half22float2(h2);
                __half2 l2 = __floats2half2_rn(f.x - bk.x, f.y - bk.y);
                ph[t][rh] = *reinterpret_cast<uint32_t*>(&h2);
                pl[t][rh] = *reinterpret_cast<uint32_t*>(&l2);
            }

        // ---- O += P V (2-term: (Ph+Pl)*Vh), term-major per jc slice ----
        const int vrow = ((lane >> 4) & 1) * 8 + (lane & 7);
        const int vcol = ((lane >> 3) & 1) * 8;
#pragma unroll
        for (int jc = 0; jc < 4; jc++) {
            uint32_t pa_h[4] = {ph[2 * jc][0], ph[2 * jc][1],
                                ph[2 * jc + 1][0], ph[2 * jc + 1][1]};
            uint32_t pa_l[4] = {pl[2 * jc][0], pl[2 * jc][1],
                                pl[2 * jc + 1][0], pl[2 * jc + 1][1]};
            uint32_t vbh[4][4];
#pragma unroll
            for (int dt = 0; dt < 4; dt++) {
                const uint32_t va = ((jc * 16 + vrow) * AS + dt * 16 + vcol) * 2;
                ldsm_x4_t(vbh[dt], sVh + va);
            }
#pragma unroll
            for (int dt = 0; dt < 4; dt++)
#pragma unroll
                for (int hh = 0; hh < 2; hh++)
                    mma_fp16(oacc[dt * 2 + hh], pa_h,
                             vbh[dt][hh], vbh[dt][hh + 2]);
#pragma unroll
            for (int dt = 0; dt < 4; dt++)
#pragma unroll
                for (int hh = 0; hh < 2; hh++)
                    mma_fp16(oacc[dt * 2 + hh], pa_l,
                             vbh[dt][hh], vbh[dt][hh + 2]);
        }
    }

    // epilogue: write y single fp16 (feeds 1-term proj GEMM)
    const float inv0 = 1.f / l[0], inv1 = 1.f / l[1];
    const int row0 = q0 + wid * 16 + g;
#pragma unroll
    for (int t = 0; t < 8; t++) {
        const int col = h * HD + t * 8 + 2 * tig;
        const size_t o0i = ((size_t)b * SEQ + row0) * D_MODEL + col;
        const size_t o1i = ((size_t)b * SEQ + row0 + 8) * D_MODEL + col;
        __half2 h0 = __floats2half2_rn(oacc[t][0] * inv0, oacc[t][1] * inv0);
        __half2 h1 = __floats2half2_rn(oacc[t][2] * inv1, oacc[t][3] * inv1);
        *reinterpret_cast<__half2*>(yh + o0i) = h0;
        *reinterpret_cast<__half2*>(yh + o1i) = h1;
    }
}

// ---------------------------------------------------------------------------
extern "C" void kernel_launch(void* const* d_in, const int* in_sizes, int n_in,
                              void* d_out, int out_size)
{
    const float* x      = (const float*)d_in[0];
    const float* W_attn = (const float*)d_in[1];
    const float* b_attn = (const float*)d_in[2];
    const float* W_proj = (const float*)d_in[3];
    const float* b_proj = (const float*)d_in[4];
    float* out = (float*)d_out;

    __half *xh, *yh, *qvh, *qvl, *wat, *wpt;
    cudaGetSymbolAddress((void**)&xh, g_x_hi);
    cudaGetSymbolAddress((void**)&yh, g_y_hi);
    cudaGetSymbolAddress((void**)&qvh, g_qkv_hi);
    cudaGetSymbolAddress((void**)&qvl, g_qkv_lo);
    cudaGetSymbolAddress((void**)&wat, g_wat);
    cudaGetSymbolAddress((void**)&wpt, g_wpt);

    cudaFuncSetAttribute((const void*)gemm_mma_kernel<1, true>,
                         cudaFuncAttributeMaxDynamicSharedMemorySize, GEMM_SMEM_1T);
    cudaFuncSetAttribute((const void*)gemm_mma_kernel<1, false>,
                         cudaFuncAttributeMaxDynamicSharedMemorySize, GEMM_SMEM_1T);
    cudaFuncSetAttribute((const void*)attn_mma_kernel,
                         cudaFuncAttributeMaxDynamicSharedMemorySize, ATTN_SMEM);

    const int NX = M_TOTAL * KDIM;

    // prep: x -> single fp16; weights -> fp16 transposed
    convert_half_kernel<<<NX / (256 * 4), 256>>>(x, xh, NX);
    transpose_half_kernel<<<dim3(QKV_N / 32, KDIM / 32), dim3(32, 8)>>>(
        W_attn, wat, KDIM, QKV_N);
    transpose_half_kernel<<<dim3(D_MODEL / 32, KDIM / 32), dim3(32, 8)>>>(
        W_proj, wpt, KDIM, D_MODEL);

    // 1) qkv = x @ W_attn + b_attn (1-term) -> fp16 hi/lo (exact split of result)
    gemm_mma_kernel<1, true><<<dim3(QKV_N / 128, M_TOTAL / 128), 256, GEMM_SMEM_1T>>>(
        xh, nullptr, wat, b_attn, nullptr, qvh, qvl, QKV_N);

    // 2) flash attention (S 2-term, PV 2-term) -> y single fp16
    attn_mma_kernel<<<dim3(SEQ / 64, BATCH * N_HEADS), 128, ATTN_SMEM>>>(
        qvh, qvl, yh);

    // 3) out = y @ W_proj + b_proj (1-term: terminal output)
    gemm_mma_kernel<1, false><<<dim3(D_MODEL / 128, M_TOTAL / 128), 256, GEMM_SMEM_1T>>>(
        yh, nullptr, wpt, b_proj, out, nullptr, nullptr, D_MODEL);
}